// round 12
// baseline (speedup 1.0000x reference)
#include <cuda_runtime.h>
#include <cstdint>

typedef unsigned long long u64;

// ---------------------------------------------------------------------------
// BinaryNet forward, fully bitwise. R12: 64-thread blocks (single fully
// resident wave, 28 warps/SM), STS.128 ballot batching, tightened conv1.
// Single fused kernel: warp-local table builds hidden behind the software-
// pipelined ballot-load; one __syncthreads; bitwise compute.
// ---------------------------------------------------------------------------

__global__ __launch_bounds__(64, 14) void bnn_kernel(const float* __restrict__ x,
                                                     const float* __restrict__ w1,
                                                     const float* __restrict__ w2,
                                                     const float* __restrict__ w3,
                                                     const float* __restrict__ wfc1,
                                                     const float* __restrict__ wfc2,
                                                     float* __restrict__ out, int B) {
    // 64 threads = 2 warps, 1 image/thread, warp-local bitstreams.
    __shared__ __align__(16) uint32_t sbits[2][228];  // 225 words + pad (16B-aligned rows)
    __shared__ uint32_t s_lut1w[128];      // 512B conv1 LUT (9-bit patch -> 4 ch bits)
    __shared__ u64      sT[384];           // conv2 row LUTs [(r*2+h)*64+e], byte o = popc6
    __shared__ uint32_t s_w3a[16], s_w3b[16], s_w3c[16];
    __shared__ uint32_t s_wfc1[8];
    __shared__ uint32_t s_wfc2;

    const int tid  = threadIdx.x;
    const int wrp  = tid >> 5;
    const int lane = tid & 31;

    // ---- Phase 0: warp-local table construction (no block barriers) ----
    if (wrp == 0) {
        // lanes 0-3 pack w1 channels, broadcast, all lanes build conv1 LUT
        uint32_t p = 0;
        if (lane < 4) {
            #pragma unroll
            for (int k = 0; k < 9; k++) p |= (uint32_t)(w1[lane * 9 + k] > 0.0f) << k;
        }
        uint32_t wa = __shfl_sync(0xFFFFFFFFu, p, 0);
        uint32_t wbq = __shfl_sync(0xFFFFFFFFu, p, 1);
        uint32_t wc = __shfl_sync(0xFFFFFFFFu, p, 2);
        uint32_t wd = __shfl_sync(0xFFFFFFFFu, p, 3);
        #pragma unroll
        for (int e = lane; e < 512; e += 32) {
            uint32_t nib =  (uint32_t)(__popc((uint32_t)e ^ wa)  <= 4)
                         | ((uint32_t)(__popc((uint32_t)e ^ wbq) <= 4) << 1)
                         | ((uint32_t)(__popc((uint32_t)e ^ wc)  <= 4) << 2)
                         | ((uint32_t)(__popc((uint32_t)e ^ wd)  <= 4) << 3);
            ((uint8_t*)s_lut1w)[e] = (uint8_t)nib;
        }
        if (lane < 16) {       // conv3 weights, pixel-major: bit (pix*8 + ic)
            uint32_t a = 0, b = 0, c = 0;
            for (int ic = 0; ic < 8; ic++)
                #pragma unroll
                for (int pix = 0; pix < 9; pix++) {
                    uint32_t bit = (uint32_t)(w3[(lane * 8 + ic) * 9 + pix] > 0.0f);
                    if (pix < 4)      a |= bit << (pix * 8 + ic);
                    else if (pix < 8) b |= bit << ((pix - 4) * 8 + ic);
                    else              c |= bit << ic;
                }
            s_w3a[lane] = a; s_w3b[lane] = b; s_w3c[lane] = c;
        } else if (lane < 24) { // fc1 rows
            int o = lane - 16;
            uint32_t qv = 0;
            #pragma unroll
            for (int j = 0; j < 16; j++) qv |= (uint32_t)(wfc1[o * 16 + j] > 0.0f) << j;
            s_wfc1[o] = qv;
        } else if (lane == 24) {
            uint32_t pp = 0;
            #pragma unroll
            for (int j = 0; j < 8; j++) pp |= (uint32_t)(wfc2[j] > 0.0f) << j;
            s_wfc2 = pp;
        }
    } else {
        // lanes 0-7 pack w2 output channels, broadcast 8x u64, build conv2 LUTs
        u64 p = 0;
        if (lane < 8) {
            for (int ic = 0; ic < 4; ic++)
                #pragma unroll
                for (int k = 0; k < 9; k++)
                    p |= (u64)(w2[(lane * 4 + ic) * 9 + k] > 0.0f) << (k * 4 + ic);
        }
        uint32_t plo = (uint32_t)p, phi = (uint32_t)(p >> 32);
        u64 w2r[8];
        #pragma unroll
        for (int o = 0; o < 8; o++) {
            uint32_t lo = __shfl_sync(0xFFFFFFFFu, plo, o);
            uint32_t hi = __shfl_sync(0xFFFFFFFFu, phi, o);
            w2r[o] = ((u64)hi << 32) | lo;
        }
        #pragma unroll
        for (int t = lane; t < 384; t += 32) {
            int tab = t >> 6, e = t & 63;
            int sh  = (tab >> 1) * 12 + (tab & 1) * 6;
            u64 val = 0;
            #pragma unroll
            for (int o = 0; o < 8; o++)
                val |= (u64)__popc((uint32_t)e ^ (uint32_t)((w2r[o] >> sh) & 63)) << (8 * o);
            sT[t] = val;
        }
    }

    // ---- Phase 1: software-pipelined coalesced load + ballot binarization ----
    // 225 words/warp = 28 chunks of 8 + 1 tail word. STS.128 from lane 0.
    const int warpBase = blockIdx.x * (64 * 225) + wrp * (32 * 225);
    const int total    = B * 225;
    uint32_t* wb = sbits[wrp];

    if (warpBase + 225 * 32 <= total) {
        const float* xp = x + warpBase + lane;
        float c0[8], c1[8];
        #pragma unroll
        for (int j = 0; j < 8; j++) c0[j] = __ldg(xp + 32 * j);
        #pragma unroll
        for (int j = 0; j < 8; j++) c1[j] = __ldg(xp + 256 + 32 * j);

        #pragma unroll 1
        for (int c = 0; c < 26; c += 2) {
            uint32_t bb[8];
            #pragma unroll
            for (int j = 0; j < 8; j++) bb[j] = __ballot_sync(0xFFFFFFFFu, c0[j] > 0.0f);
            if (lane == 0) {
                *(uint4*)(wb + c * 8)     = make_uint4(bb[0], bb[1], bb[2], bb[3]);
                *(uint4*)(wb + c * 8 + 4) = make_uint4(bb[4], bb[5], bb[6], bb[7]);
            }
            #pragma unroll
            for (int j = 0; j < 8; j++) c0[j] = __ldg(xp + (c + 2) * 256 + 32 * j);
            #pragma unroll
            for (int j = 0; j < 8; j++) bb[j] = __ballot_sync(0xFFFFFFFFu, c1[j] > 0.0f);
            if (lane == 0) {
                *(uint4*)(wb + (c + 1) * 8)     = make_uint4(bb[0], bb[1], bb[2], bb[3]);
                *(uint4*)(wb + (c + 1) * 8 + 4) = make_uint4(bb[4], bb[5], bb[6], bb[7]);
            }
            #pragma unroll
            for (int j = 0; j < 8; j++) c1[j] = __ldg(xp + (c + 3) * 256 + 32 * j);
        }
        {   // chunks 26, 27 (already in c0/c1), word 224
            uint32_t bb[8];
            #pragma unroll
            for (int j = 0; j < 8; j++) bb[j] = __ballot_sync(0xFFFFFFFFu, c0[j] > 0.0f);
            if (lane == 0) {
                *(uint4*)(wb + 26 * 8)     = make_uint4(bb[0], bb[1], bb[2], bb[3]);
                *(uint4*)(wb + 26 * 8 + 4) = make_uint4(bb[4], bb[5], bb[6], bb[7]);
            }
            #pragma unroll
            for (int j = 0; j < 8; j++) bb[j] = __ballot_sync(0xFFFFFFFFu, c1[j] > 0.0f);
            if (lane == 0) {
                *(uint4*)(wb + 27 * 8)     = make_uint4(bb[0], bb[1], bb[2], bb[3]);
                *(uint4*)(wb + 27 * 8 + 4) = make_uint4(bb[4], bb[5], bb[6], bb[7]);
            }
            float v = __ldg(xp + 224 * 32);
            uint32_t b = __ballot_sync(0xFFFFFFFFu, v > 0.0f);
            if (lane == 0) wb[224] = b;
        }
    } else {
        for (int k = 0; k < 225; k++) {
            int idx = warpBase + k * 32 + lane;
            float v = (idx < total) ? __ldg(x + idx) : 0.0f;
            uint32_t b = __ballot_sync(0xFFFFFFFFu, v > 0.0f);
            if (lane == 0) wb[k] = b;
        }
    }

    __syncthreads();   // tables + own bitstream visible

    // ---- Phase 2: compute ----
    const uint8_t* lut1 = (const uint8_t*)s_lut1w;
    const int base = lane * 225;

    // extract 15 rows of 15 bits (upper bits garbage, masked during use)
    uint32_t rows[15];
    #pragma unroll
    for (int r = 0; r < 15; r++) {
        int off = base + r * 15;
        rows[r] = __funnelshift_r(wb[off >> 5], wb[(off >> 5) + 1], off & 31);
    }

    // conv1: 7x7, 4 channels, nibble-packed rows
    uint32_t q[7];
    #pragma unroll
    for (int orow = 0; orow < 7; orow++) {
        uint32_t M   = (rows[2 * orow] & 0x7FFFu) | (rows[2 * orow + 1] << 16);
        uint32_t r2v = rows[2 * orow + 2] << 6;
        uint32_t acc = 0;
        #pragma unroll
        for (int oc = 0; oc < 7; oc++) {
            uint32_t t = M >> (2 * oc);
            uint32_t patch = (t & 7u) | ((t >> 13) & 0x38u) | ((r2v >> (2 * oc)) & 0x1C0u);
            acc += (uint32_t)lut1[patch] << (4 * oc);
        }
        q[orow] = acc;
    }

    // conv2: 3x3, 8 channels, ternary; 6-bit row LUTs + byte-SIMD compares
    uint32_t v2a = 0, v2b = 0, v2c = 0, m2a = 0, m2b = 0, m2c = 0;
    #pragma unroll
    for (int R = 0; R < 3; R++) {
        uint32_t q0 = q[2 * R], q1 = q[2 * R + 1], q2 = q[2 * R + 2];
        #pragma unroll
        for (int C = 0; C < 3; C++) {
            uint32_t r0 = (q0 >> (8 * C)) & 0xFFFu;
            uint32_t r1 = (q1 >> (8 * C)) & 0xFFFu;
            uint32_t r2 = (q2 >> (8 * C)) & 0xFFFu;
            u64 d8 = sT[r0 & 63] + sT[64 + (r0 >> 6)]
                   + sT[128 + (r1 & 63)] + sT[192 + (r1 >> 6)]
                   + sT[256 + (r2 & 63)] + sT[320 + (r2 >> 6)];
            uint32_t dlo = (uint32_t)d8, dhi = (uint32_t)(d8 >> 32);
            // per-byte d in [0,36]: bit7(d+110) <=> d>=18 ; bit7(d+109) <=> d>=19
            uint32_t a18l = dlo + 0x6E6E6E6Eu, a18h = dhi + 0x6E6E6E6Eu;
            uint32_t a19l = dlo + 0x6D6D6D6Du, a19h = dhi + 0x6D6D6D6Du;
            uint32_t vl = (~a18l) & 0x80808080u;            // d<18  (sum>0)
            uint32_t vh = (~a18h) & 0x80808080u;
            uint32_t ml = ((~a18l) | a19l) & 0x80808080u;   // d!=18 (sum!=0)
            uint32_t mh = ((~a18h) | a19h) & 0x80808080u;
            uint32_t vbt = ((vl * 0x00204081u) >> 28) | (((vh * 0x00204081u) >> 28) << 4);
            uint32_t mbt = ((ml * 0x00204081u) >> 28) | (((mh * 0x00204081u) >> 28) << 4);
            const int pix = R * 3 + C;
            if (pix < 4)      { v2a |= vbt << (8 * pix);       m2a |= mbt << (8 * pix); }
            else if (pix < 8) { v2b |= vbt << (8 * (pix - 4)); m2b |= mbt << (8 * (pix - 4)); }
            else              { v2c = vbt;                     m2c = mbt; }
        }
    }

    // conv3: 16 channels, ternary
    const int mc2 = __popc(m2a) + __popc(m2b) + __popc(m2c);
    uint32_t v3 = 0, m3 = 0;
    #pragma unroll
    for (int o = 0; o < 16; o++) {
        int d = __popc(m2a & (v2a ^ s_w3a[o]))
              + __popc(m2b & (v2b ^ s_w3b[o]))
              + __popc(m2c & (v2c ^ s_w3c[o]));
        int s = mc2 - 2 * d;
        v3 |= (uint32_t)(s > 0)  << o;
        m3 |= (uint32_t)(s != 0) << o;
    }

    // fc1: 16 -> 8, ternary
    const int mc3 = __popc(m3);
    uint32_t v4 = 0, m4 = 0;
    #pragma unroll
    for (int o = 0; o < 8; o++) {
        int d = __popc(m3 & (v3 ^ s_wfc1[o]));
        int s = mc3 - 2 * d;
        v4 |= (uint32_t)(s > 0)  << o;
        m4 |= (uint32_t)(s != 0) << o;
    }

    // fc2: 8 -> 1, integer output
    int d5  = __popc(m4 & (v4 ^ s_wfc2));
    int res = __popc(m4) - 2 * d5;

    const int img = blockIdx.x * 64 + wrp * 32 + lane;
    if (img < B) out[img] = (float)res;
}

extern "C" void kernel_launch(void* const* d_in, const int* in_sizes, int n_in,
                              void* d_out, int out_size) {
    const float* x    = (const float*)d_in[0];
    const float* w1   = (const float*)d_in[1];
    const float* w2   = (const float*)d_in[2];
    const float* w3   = (const float*)d_in[3];
    const float* wfc1 = (const float*)d_in[4];
    const float* wfc2 = (const float*)d_in[5];
    float* out = (float*)d_out;

    int B = in_sizes[0] / 225;                 // x is [B,1,15,15]
    int blocks = (B + 63) / 64;                // 64 images/block, 2 warps
    bnn_kernel<<<blocks, 64>>>(x, w1, w2, w3, wfc1, wfc2, out, B);
}

// round 13
// speedup vs baseline: 1.0738x; 1.0738x over previous
#include <cuda_runtime.h>
#include <cstdint>

typedef unsigned long long u64;

// ---------------------------------------------------------------------------
// BinaryNet forward, fully bitwise. R13: fully-unrolled load pipeline
// (immediate LDG offsets, wide scoreboard batches), depth-2 buffers,
// dual-accumulator conv1. Otherwise R12 structure: 64-thread blocks,
// warp-local tables + bitstreams, one __syncthreads.
// ---------------------------------------------------------------------------

__global__ __launch_bounds__(64, 14) void bnn_kernel(const float* __restrict__ x,
                                                     const float* __restrict__ w1,
                                                     const float* __restrict__ w2,
                                                     const float* __restrict__ w3,
                                                     const float* __restrict__ wfc1,
                                                     const float* __restrict__ wfc2,
                                                     float* __restrict__ out, int B) {
    // 64 threads = 2 warps, 1 image/thread, warp-local bitstreams.
    __shared__ __align__(16) uint32_t sbits[2][228];  // 225 words + pad
    __shared__ uint32_t s_lut1w[128];      // 512B conv1 LUT (9-bit patch -> 4 ch bits)
    __shared__ u64      sT[384];           // conv2 row LUTs [(r*2+h)*64+e], byte o = popc6
    __shared__ uint32_t s_w3a[16], s_w3b[16], s_w3c[16];
    __shared__ uint32_t s_wfc1[8];
    __shared__ uint32_t s_wfc2;

    const int tid  = threadIdx.x;
    const int wrp  = tid >> 5;
    const int lane = tid & 31;

    // ---- Phase 0: warp-local table construction (no block barriers) ----
    if (wrp == 0) {
        uint32_t p = 0;
        if (lane < 4) {
            #pragma unroll
            for (int k = 0; k < 9; k++) p |= (uint32_t)(w1[lane * 9 + k] > 0.0f) << k;
        }
        uint32_t wa  = __shfl_sync(0xFFFFFFFFu, p, 0);
        uint32_t wbq = __shfl_sync(0xFFFFFFFFu, p, 1);
        uint32_t wc  = __shfl_sync(0xFFFFFFFFu, p, 2);
        uint32_t wd  = __shfl_sync(0xFFFFFFFFu, p, 3);
        #pragma unroll
        for (int e = lane; e < 512; e += 32) {
            uint32_t nib =  (uint32_t)(__popc((uint32_t)e ^ wa)  <= 4)
                         | ((uint32_t)(__popc((uint32_t)e ^ wbq) <= 4) << 1)
                         | ((uint32_t)(__popc((uint32_t)e ^ wc)  <= 4) << 2)
                         | ((uint32_t)(__popc((uint32_t)e ^ wd)  <= 4) << 3);
            ((uint8_t*)s_lut1w)[e] = (uint8_t)nib;
        }
        if (lane < 16) {       // conv3 weights, pixel-major: bit (pix*8 + ic)
            uint32_t a = 0, b = 0, c = 0;
            for (int ic = 0; ic < 8; ic++)
                #pragma unroll
                for (int pix = 0; pix < 9; pix++) {
                    uint32_t bit = (uint32_t)(w3[(lane * 8 + ic) * 9 + pix] > 0.0f);
                    if (pix < 4)      a |= bit << (pix * 8 + ic);
                    else if (pix < 8) b |= bit << ((pix - 4) * 8 + ic);
                    else              c |= bit << ic;
                }
            s_w3a[lane] = a; s_w3b[lane] = b; s_w3c[lane] = c;
        } else if (lane < 24) { // fc1 rows
            int o = lane - 16;
            uint32_t qv = 0;
            #pragma unroll
            for (int j = 0; j < 16; j++) qv |= (uint32_t)(wfc1[o * 16 + j] > 0.0f) << j;
            s_wfc1[o] = qv;
        } else if (lane == 24) {
            uint32_t pp = 0;
            #pragma unroll
            for (int j = 0; j < 8; j++) pp |= (uint32_t)(wfc2[j] > 0.0f) << j;
            s_wfc2 = pp;
        }
    } else {
        u64 p = 0;
        if (lane < 8) {
            for (int ic = 0; ic < 4; ic++)
                #pragma unroll
                for (int k = 0; k < 9; k++)
                    p |= (u64)(w2[(lane * 4 + ic) * 9 + k] > 0.0f) << (k * 4 + ic);
        }
        uint32_t plo = (uint32_t)p, phi = (uint32_t)(p >> 32);
        u64 w2r[8];
        #pragma unroll
        for (int o = 0; o < 8; o++) {
            uint32_t lo = __shfl_sync(0xFFFFFFFFu, plo, o);
            uint32_t hi = __shfl_sync(0xFFFFFFFFu, phi, o);
            w2r[o] = ((u64)hi << 32) | lo;
        }
        #pragma unroll
        for (int t = lane; t < 384; t += 32) {
            int tab = t >> 6, e = t & 63;
            int sh  = (tab >> 1) * 12 + (tab & 1) * 6;
            u64 val = 0;
            #pragma unroll
            for (int o = 0; o < 8; o++)
                val |= (u64)__popc((uint32_t)e ^ (uint32_t)((w2r[o] >> sh) & 63)) << (8 * o);
            sT[t] = val;
        }
    }

    // ---- Phase 1: fully-unrolled pipelined load + ballot binarization ----
    // 225 words/warp = 28 chunks of 8 + 1 tail word. Immediate LDG offsets.
    const int warpBase = blockIdx.x * (64 * 225) + wrp * (32 * 225);
    const int total    = B * 225;
    uint32_t* wb = sbits[wrp];

    if (warpBase + 225 * 32 <= total) {
        const float* xp = x + warpBase + lane;
        float c0[8], c1[8];
        #pragma unroll
        for (int j = 0; j < 8; j++) c0[j] = __ldg(xp + 32 * j);
        #pragma unroll
        for (int j = 0; j < 8; j++) c1[j] = __ldg(xp + 256 + 32 * j);

        #pragma unroll
        for (int c = 0; c < 28; c++) {
            uint32_t bb[8];
            if (c & 1) {
                #pragma unroll
                for (int j = 0; j < 8; j++) bb[j] = __ballot_sync(0xFFFFFFFFu, c1[j] > 0.0f);
            } else {
                #pragma unroll
                for (int j = 0; j < 8; j++) bb[j] = __ballot_sync(0xFFFFFFFFu, c0[j] > 0.0f);
            }
            if (lane == 0) {
                *(uint4*)(wb + c * 8)     = make_uint4(bb[0], bb[1], bb[2], bb[3]);
                *(uint4*)(wb + c * 8 + 4) = make_uint4(bb[4], bb[5], bb[6], bb[7]);
            }
            if (c + 2 < 28) {
                if (c & 1) {
                    #pragma unroll
                    for (int j = 0; j < 8; j++) c1[j] = __ldg(xp + (c + 2) * 256 + 32 * j);
                } else {
                    #pragma unroll
                    for (int j = 0; j < 8; j++) c0[j] = __ldg(xp + (c + 2) * 256 + 32 * j);
                }
            }
        }
        {   // word 224
            float v = __ldg(xp + 224 * 32);
            uint32_t b = __ballot_sync(0xFFFFFFFFu, v > 0.0f);
            if (lane == 0) wb[224] = b;
        }
    } else {
        for (int k = 0; k < 225; k++) {
            int idx = warpBase + k * 32 + lane;
            float v = (idx < total) ? __ldg(x + idx) : 0.0f;
            uint32_t b = __ballot_sync(0xFFFFFFFFu, v > 0.0f);
            if (lane == 0) wb[k] = b;
        }
    }

    __syncthreads();   // tables + own bitstream visible

    // ---- Phase 2: compute ----
    const uint8_t* lut1 = (const uint8_t*)s_lut1w;
    const int base = lane * 225;

    // extract 15 rows of 15 bits (upper bits garbage, masked during use)
    uint32_t rows[15];
    #pragma unroll
    for (int r = 0; r < 15; r++) {
        int off = base + r * 15;
        rows[r] = __funnelshift_r(wb[off >> 5], wb[(off >> 5) + 1], off & 31);
    }

    // conv1: 7x7, 4 channels, nibble-packed rows; even/odd dual accumulators
    uint32_t q[7];
    #pragma unroll
    for (int orow = 0; orow < 7; orow++) {
        uint32_t M   = (rows[2 * orow] & 0x7FFFu) | (rows[2 * orow + 1] << 16);
        uint32_t r2v = rows[2 * orow + 2] << 6;
        uint32_t acc0 = 0, acc1 = 0;
        #pragma unroll
        for (int oc = 0; oc < 7; oc++) {
            uint32_t t = M >> (2 * oc);
            uint32_t patch = (t & 7u) | ((t >> 13) & 0x38u) | ((r2v >> (2 * oc)) & 0x1C0u);
            if (oc & 1) acc1 += (uint32_t)lut1[patch] << (4 * oc);
            else        acc0 += (uint32_t)lut1[patch] << (4 * oc);
        }
        q[orow] = acc0 | acc1;
    }

    // conv2: 3x3, 8 channels, ternary; 6-bit row LUTs + byte-SIMD compares
    uint32_t v2a = 0, v2b = 0, v2c = 0, m2a = 0, m2b = 0, m2c = 0;
    #pragma unroll
    for (int R = 0; R < 3; R++) {
        uint32_t q0 = q[2 * R], q1 = q[2 * R + 1], q2 = q[2 * R + 2];
        #pragma unroll
        for (int C = 0; C < 3; C++) {
            uint32_t r0 = (q0 >> (8 * C)) & 0xFFFu;
            uint32_t r1 = (q1 >> (8 * C)) & 0xFFFu;
            uint32_t r2 = (q2 >> (8 * C)) & 0xFFFu;
            u64 d8 = sT[r0 & 63] + sT[64 + (r0 >> 6)]
                   + sT[128 + (r1 & 63)] + sT[192 + (r1 >> 6)]
                   + sT[256 + (r2 & 63)] + sT[320 + (r2 >> 6)];
            uint32_t dlo = (uint32_t)d8, dhi = (uint32_t)(d8 >> 32);
            // per-byte d in [0,36]: bit7(d+110) <=> d>=18 ; bit7(d+109) <=> d>=19
            uint32_t a18l = dlo + 0x6E6E6E6Eu, a18h = dhi + 0x6E6E6E6Eu;
            uint32_t a19l = dlo + 0x6D6D6D6Du, a19h = dhi + 0x6D6D6D6Du;
            uint32_t vl = (~a18l) & 0x80808080u;            // d<18  (sum>0)
            uint32_t vh = (~a18h) & 0x80808080u;
            uint32_t ml = ((~a18l) | a19l) & 0x80808080u;   // d!=18 (sum!=0)
            uint32_t mh = ((~a18h) | a19h) & 0x80808080u;
            uint32_t vbt = ((vl * 0x00204081u) >> 28) | (((vh * 0x00204081u) >> 28) << 4);
            uint32_t mbt = ((ml * 0x00204081u) >> 28) | (((mh * 0x00204081u) >> 28) << 4);
            const int pix = R * 3 + C;
            if (pix < 4)      { v2a |= vbt << (8 * pix);       m2a |= mbt << (8 * pix); }
            else if (pix < 8) { v2b |= vbt << (8 * (pix - 4)); m2b |= mbt << (8 * (pix - 4)); }
            else              { v2c = vbt;                     m2c = mbt; }
        }
    }

    // conv3: 16 channels, ternary
    const int mc2 = __popc(m2a) + __popc(m2b) + __popc(m2c);
    uint32_t v3 = 0, m3 = 0;
    #pragma unroll
    for (int o = 0; o < 16; o++) {
        int d = __popc(m2a & (v2a ^ s_w3a[o]))
              + __popc(m2b & (v2b ^ s_w3b[o]))
              + __popc(m2c & (v2c ^ s_w3c[o]));
        int s = mc2 - 2 * d;
        v3 |= (uint32_t)(s > 0)  << o;
        m3 |= (uint32_t)(s != 0) << o;
    }

    // fc1: 16 -> 8, ternary
    const int mc3 = __popc(m3);
    uint32_t v4 = 0, m4 = 0;
    #pragma unroll
    for (int o = 0; o < 8; o++) {
        int d = __popc(m3 & (v3 ^ s_wfc1[o]));
        int s = mc3 - 2 * d;
        v4 |= (uint32_t)(s > 0)  << o;
        m4 |= (uint32_t)(s != 0) << o;
    }

    // fc2: 8 -> 1, integer output
    int d5  = __popc(m4 & (v4 ^ s_wfc2));
    int res = __popc(m4) - 2 * d5;

    const int img = blockIdx.x * 64 + wrp * 32 + lane;
    if (img < B) out[img] = (float)res;
}

extern "C" void kernel_launch(void* const* d_in, const int* in_sizes, int n_in,
                              void* d_out, int out_size) {
    const float* x    = (const float*)d_in[0];
    const float* w1   = (const float*)d_in[1];
    const float* w2   = (const float*)d_in[2];
    const float* w3   = (const float*)d_in[3];
    const float* wfc1 = (const float*)d_in[4];
    const float* wfc2 = (const float*)d_in[5];
    float* out = (float*)d_out;

    int B = in_sizes[0] / 225;                 // x is [B,1,15,15]
    int blocks = (B + 63) / 64;                // 64 images/block, 2 warps
    bnn_kernel<<<blocks, 64>>>(x, w1, w2, w3, wfc1, wfc2, out, B);
}

// round 14
// speedup vs baseline: 1.0883x; 1.0135x over previous
#include <cuda_runtime.h>
#include <cstdint>

typedef unsigned long long u64;

// ---------------------------------------------------------------------------
// BinaryNet forward, fully bitwise. R14: cp.async (LDGSTS) deep-pipelined
// input streaming through a 4-slot smem ring (fire-and-forget loads; warp
// critical path sees only LDS latency) + ballot binarization from smem.
// Compute path unchanged from R13 (conv1 LUT dual-acc, conv2 6-bit row LUTs
// + byte-SIMD, conv3/fc ternary popcount).
// ---------------------------------------------------------------------------

__device__ __forceinline__ void cp_async16(uint32_t sm_dst, const void* gsrc) {
    asm volatile("cp.async.cg.shared.global [%0], [%1], 16;\n"
                 :: "r"(sm_dst), "l"(gsrc) : "memory");
}
__device__ __forceinline__ void cp_commit() {
    asm volatile("cp.async.commit_group;\n" ::: "memory");
}
__device__ __forceinline__ void cp_wait3() {
    asm volatile("cp.async.wait_group 3;\n" ::: "memory");
}

__global__ __launch_bounds__(64, 14) void bnn_kernel(const float* __restrict__ x,
                                                     const float* __restrict__ w1,
                                                     const float* __restrict__ w2,
                                                     const float* __restrict__ w3,
                                                     const float* __restrict__ wfc1,
                                                     const float* __restrict__ wfc2,
                                                     float* __restrict__ out, int B) {
    // 64 threads = 2 warps, 1 image/thread, warp-local bitstreams.
    __shared__ __align__(16) float    sraw[2][4][256];   // per-warp 4-slot chunk ring (1KB slots)
    __shared__ __align__(16) uint32_t sbits[2][228];     // 225 words + pad
    __shared__ uint32_t s_lut1w[128];      // 512B conv1 LUT (9-bit patch -> 4 ch bits)
    __shared__ u64      sT[384];           // conv2 row LUTs [(r*2+h)*64+e], byte o = popc6
    __shared__ uint32_t s_w3a[16], s_w3b[16], s_w3c[16];
    __shared__ uint32_t s_wfc1[8];
    __shared__ uint32_t s_wfc2;

    const int tid  = threadIdx.x;
    const int wrp  = tid >> 5;
    const int lane = tid & 31;

    // ---- Phase 0: warp-local table construction (no block barriers) ----
    if (wrp == 0) {
        uint32_t p = 0;
        if (lane < 4) {
            #pragma unroll
            for (int k = 0; k < 9; k++) p |= (uint32_t)(w1[lane * 9 + k] > 0.0f) << k;
        }
        uint32_t wa  = __shfl_sync(0xFFFFFFFFu, p, 0);
        uint32_t wbq = __shfl_sync(0xFFFFFFFFu, p, 1);
        uint32_t wc  = __shfl_sync(0xFFFFFFFFu, p, 2);
        uint32_t wd  = __shfl_sync(0xFFFFFFFFu, p, 3);
        #pragma unroll
        for (int e = lane; e < 512; e += 32) {
            uint32_t nib =  (uint32_t)(__popc((uint32_t)e ^ wa)  <= 4)
                         | ((uint32_t)(__popc((uint32_t)e ^ wbq) <= 4) << 1)
                         | ((uint32_t)(__popc((uint32_t)e ^ wc)  <= 4) << 2)
                         | ((uint32_t)(__popc((uint32_t)e ^ wd)  <= 4) << 3);
            ((uint8_t*)s_lut1w)[e] = (uint8_t)nib;
        }
        if (lane < 16) {       // conv3 weights, pixel-major: bit (pix*8 + ic)
            uint32_t a = 0, b = 0, c = 0;
            for (int ic = 0; ic < 8; ic++)
                #pragma unroll
                for (int pix = 0; pix < 9; pix++) {
                    uint32_t bit = (uint32_t)(w3[(lane * 8 + ic) * 9 + pix] > 0.0f);
                    if (pix < 4)      a |= bit << (pix * 8 + ic);
                    else if (pix < 8) b |= bit << ((pix - 4) * 8 + ic);
                    else              c |= bit << ic;
                }
            s_w3a[lane] = a; s_w3b[lane] = b; s_w3c[lane] = c;
        } else if (lane < 24) { // fc1 rows
            int o = lane - 16;
            uint32_t qv = 0;
            #pragma unroll
            for (int j = 0; j < 16; j++) qv |= (uint32_t)(wfc1[o * 16 + j] > 0.0f) << j;
            s_wfc1[o] = qv;
        } else if (lane == 24) {
            uint32_t pp = 0;
            #pragma unroll
            for (int j = 0; j < 8; j++) pp |= (uint32_t)(wfc2[j] > 0.0f) << j;
            s_wfc2 = pp;
        }
    } else {
        u64 p = 0;
        if (lane < 8) {
            for (int ic = 0; ic < 4; ic++)
                #pragma unroll
                for (int k = 0; k < 9; k++)
                    p |= (u64)(w2[(lane * 4 + ic) * 9 + k] > 0.0f) << (k * 4 + ic);
        }
        uint32_t plo = (uint32_t)p, phi = (uint32_t)(p >> 32);
        u64 w2r[8];
        #pragma unroll
        for (int o = 0; o < 8; o++) {
            uint32_t lo = __shfl_sync(0xFFFFFFFFu, plo, o);
            uint32_t hi = __shfl_sync(0xFFFFFFFFu, phi, o);
            w2r[o] = ((u64)hi << 32) | lo;
        }
        #pragma unroll
        for (int t = lane; t < 384; t += 32) {
            int tab = t >> 6, e = t & 63;
            int sh  = (tab >> 1) * 12 + (tab & 1) * 6;
            u64 val = 0;
            #pragma unroll
            for (int o = 0; o < 8; o++)
                val |= (u64)__popc((uint32_t)e ^ (uint32_t)((w2r[o] >> sh) & 63)) << (8 * o);
            sT[t] = val;
        }
    }

    // ---- Phase 1: cp.async-pipelined load + ballot binarization ----
    // 225 words/warp = 28 chunks of 8 words (256 floats, 1KB) + 1 tail word.
    const int warpBase = blockIdx.x * (64 * 225) + wrp * (32 * 225);
    const int total    = B * 225;
    uint32_t* wb = sbits[wrp];
    float*    rw = &sraw[wrp][0][0];

    if (warpBase + 225 * 32 <= total) {
        const float* xp = x + warpBase;               // warp's 7200-float stream
        // smem byte addresses for this lane's two 16B segments per slot
        uint32_t smBase = (uint32_t)__cvta_generic_to_shared(rw) + lane * 16u;

        // prologue: issue chunks 0..3 (one commit group each)
        #pragma unroll
        for (int c = 0; c < 4; c++) {
            cp_async16(smBase + c * 1024u,        xp + c * 256 + lane * 4);
            cp_async16(smBase + c * 1024u + 512u, xp + c * 256 + 128 + lane * 4);
            cp_commit();
        }

        #pragma unroll
        for (int c = 0; c < 28; c++) {
            cp_wait3();                 // chunk c resident
            __syncwarp();
            const float* buf = rw + (c & 3) * 256;
            uint32_t bb[8];
            #pragma unroll
            for (int j = 0; j < 8; j++) {
                float v = buf[j * 32 + lane];
                bb[j] = __ballot_sync(0xFFFFFFFFu, v > 0.0f);
            }
            __syncwarp();               // all lanes done reading slot before overwrite
            if (lane == 0) {
                *(uint4*)(wb + c * 8)     = make_uint4(bb[0], bb[1], bb[2], bb[3]);
                *(uint4*)(wb + c * 8 + 4) = make_uint4(bb[4], bb[5], bb[6], bb[7]);
            }
            if (c + 4 < 28) {
                cp_async16(smBase + ((c + 4) & 3) * 1024u,        xp + (c + 4) * 256 + lane * 4);
                cp_async16(smBase + ((c + 4) & 3) * 1024u + 512u, xp + (c + 4) * 256 + 128 + lane * 4);
            }
            cp_commit();                // empty groups in tail keep wait arithmetic valid
        }
        {   // word 224
            float v = __ldg(xp + 224 * 32 + lane);
            uint32_t b = __ballot_sync(0xFFFFFFFFu, v > 0.0f);
            if (lane == 0) wb[224] = b;
        }
    } else {
        for (int k = 0; k < 225; k++) {
            int idx = warpBase + k * 32 + lane;
            float v = (idx < total) ? __ldg(x + idx) : 0.0f;
            uint32_t b = __ballot_sync(0xFFFFFFFFu, v > 0.0f);
            if (lane == 0) wb[k] = b;
        }
    }

    __syncthreads();   // tables + own bitstream visible

    // ---- Phase 2: compute ----
    const uint8_t* lut1 = (const uint8_t*)s_lut1w;
    const int base = lane * 225;

    // extract 15 rows of 15 bits (upper bits garbage, masked during use)
    uint32_t rows[15];
    #pragma unroll
    for (int r = 0; r < 15; r++) {
        int off = base + r * 15;
        rows[r] = __funnelshift_r(wb[off >> 5], wb[(off >> 5) + 1], off & 31);
    }

    // conv1: 7x7, 4 channels, nibble-packed rows; even/odd dual accumulators
    uint32_t q[7];
    #pragma unroll
    for (int orow = 0; orow < 7; orow++) {
        uint32_t M   = (rows[2 * orow] & 0x7FFFu) | (rows[2 * orow + 1] << 16);
        uint32_t r2v = rows[2 * orow + 2] << 6;
        uint32_t acc0 = 0, acc1 = 0;
        #pragma unroll
        for (int oc = 0; oc < 7; oc++) {
            uint32_t t = M >> (2 * oc);
            uint32_t patch = (t & 7u) | ((t >> 13) & 0x38u) | ((r2v >> (2 * oc)) & 0x1C0u);
            if (oc & 1) acc1 += (uint32_t)lut1[patch] << (4 * oc);
            else        acc0 += (uint32_t)lut1[patch] << (4 * oc);
        }
        q[orow] = acc0 | acc1;
    }

    // conv2: 3x3, 8 channels, ternary; 6-bit row LUTs + byte-SIMD compares
    uint32_t v2a = 0, v2b = 0, v2c = 0, m2a = 0, m2b = 0, m2c = 0;
    #pragma unroll
    for (int R = 0; R < 3; R++) {
        uint32_t q0 = q[2 * R], q1 = q[2 * R + 1], q2 = q[2 * R + 2];
        #pragma unroll
        for (int C = 0; C < 3; C++) {
            uint32_t r0 = (q0 >> (8 * C)) & 0xFFFu;
            uint32_t r1 = (q1 >> (8 * C)) & 0xFFFu;
            uint32_t r2 = (q2 >> (8 * C)) & 0xFFFu;
            u64 d8 = sT[r0 & 63] + sT[64 + (r0 >> 6)]
                   + sT[128 + (r1 & 63)] + sT[192 + (r1 >> 6)]
                   + sT[256 + (r2 & 63)] + sT[320 + (r2 >> 6)];
            uint32_t dlo = (uint32_t)d8, dhi = (uint32_t)(d8 >> 32);
            // per-byte d in [0,36]: bit7(d+110) <=> d>=18 ; bit7(d+109) <=> d>=19
            uint32_t a18l = dlo + 0x6E6E6E6Eu, a18h = dhi + 0x6E6E6E6Eu;
            uint32_t a19l = dlo + 0x6D6D6D6Du, a19h = dhi + 0x6D6D6D6Du;
            uint32_t vl = (~a18l) & 0x80808080u;            // d<18  (sum>0)
            uint32_t vh = (~a18h) & 0x80808080u;
            uint32_t ml = ((~a18l) | a19l) & 0x80808080u;   // d!=18 (sum!=0)
            uint32_t mh = ((~a18h) | a19h) & 0x80808080u;
            uint32_t vbt = ((vl * 0x00204081u) >> 28) | (((vh * 0x00204081u) >> 28) << 4);
            uint32_t mbt = ((ml * 0x00204081u) >> 28) | (((mh * 0x00204081u) >> 28) << 4);
            const int pix = R * 3 + C;
            if (pix < 4)      { v2a |= vbt << (8 * pix);       m2a |= mbt << (8 * pix); }
            else if (pix < 8) { v2b |= vbt << (8 * (pix - 4)); m2b |= mbt << (8 * (pix - 4)); }
            else              { v2c = vbt;                     m2c = mbt; }
        }
    }

    // conv3: 16 channels, ternary
    const int mc2 = __popc(m2a) + __popc(m2b) + __popc(m2c);
    uint32_t v3 = 0, m3 = 0;
    #pragma unroll
    for (int o = 0; o < 16; o++) {
        int d = __popc(m2a & (v2a ^ s_w3a[o]))
              + __popc(m2b & (v2b ^ s_w3b[o]))
              + __popc(m2c & (v2c ^ s_w3c[o]));
        int s = mc2 - 2 * d;
        v3 |= (uint32_t)(s > 0)  << o;
        m3 |= (uint32_t)(s != 0) << o;
    }

    // fc1: 16 -> 8, ternary
    const int mc3 = __popc(m3);
    uint32_t v4 = 0, m4 = 0;
    #pragma unroll
    for (int o = 0; o < 8; o++) {
        int d = __popc(m3 & (v3 ^ s_wfc1[o]));
        int s = mc3 - 2 * d;
        v4 |= (uint32_t)(s > 0)  << o;
        m4 |= (uint32_t)(s != 0) << o;
    }

    // fc2: 8 -> 1, integer output
    int d5  = __popc(m4 & (v4 ^ s_wfc2));
    int res = __popc(m4) - 2 * d5;

    const int img = blockIdx.x * 64 + wrp * 32 + lane;
    if (img < B) out[img] = (float)res;
}

extern "C" void kernel_launch(void* const* d_in, const int* in_sizes, int n_in,
                              void* d_out, int out_size) {
    const float* x    = (const float*)d_in[0];
    const float* w1   = (const float*)d_in[1];
    const float* w2   = (const float*)d_in[2];
    const float* w3   = (const float*)d_in[3];
    const float* wfc1 = (const float*)d_in[4];
    const float* wfc2 = (const float*)d_in[5];
    float* out = (float*)d_out;

    int B = in_sizes[0] / 225;                 // x is [B,1,15,15]
    int blocks = (B + 63) / 64;                // 64 images/block, 2 warps
    bnn_kernel<<<blocks, 64>>>(x, w1, w2, w3, wfc1, wfc2, out, B);
}